// round 12
// baseline (speedup 1.0000x reference)
#include <cuda_runtime.h>
#include <cuda_fp16.h>
#include <cstdint>
#include <math.h>

#define M_DIM 1024
#define U_DIM 2048
#define N_DIM 8192
#define K_DIM 4096

#define BM 128
#define BUT 32
#define BK 64                                 // k per stage
#define STAGES 3
#define STG_BYTES 32768                       // A 16K + B 16K
#define SMEM_BYTES (STAGES * STG_BYTES)       // 98304 -> 2 CTAs/SM
#define B_OFF 16384
#define EP_STRIDE 132
#define NKT (K_DIM / BK)                      // 64

// Plain fp16 operands: A row-major [M][K]; W transposed K-major [N][K]
__device__ __align__(1024) __half g_ah[(size_t)M_DIM * K_DIM];   // 8 MB
__device__ __align__(1024) __half g_wh[(size_t)N_DIM * K_DIM];   // 64 MB

// ---------------------------------------------------------------------------
__device__ __forceinline__ void cp16(uint32_t dst, const void* src) {
    asm volatile("cp.async.cg.shared.global [%0], [%1], 16;" :: "r"(dst), "l"(src));
}
#define CP_COMMIT() asm volatile("cp.async.commit_group;" ::: "memory")
#define CP_WAIT1()  asm volatile("cp.async.wait_group 1;" ::: "memory")

__device__ __forceinline__ void ldsm4(uint32_t* r, uint32_t addr) {
    asm volatile("ldmatrix.sync.aligned.m8n8.x4.shared.b16 {%0,%1,%2,%3}, [%4];"
                 : "=r"(r[0]), "=r"(r[1]), "=r"(r[2]), "=r"(r[3]) : "r"(addr));
}

__device__ __forceinline__ void mma16(float* d, uint32_t a0, uint32_t a1,
                                      uint32_t a2, uint32_t a3,
                                      uint32_t b0, uint32_t b1) {
    asm volatile(
        "mma.sync.aligned.m16n8k16.row.col.f32.f16.f16.f32 "
        "{%0,%1,%2,%3}, {%4,%5,%6,%7}, {%8,%9}, {%0,%1,%2,%3};"
        : "+f"(d[0]), "+f"(d[1]), "+f"(d[2]), "+f"(d[3])
        : "r"(a0), "r"(a1), "r"(a2), "r"(a3), "r"(b0), "r"(b1));
}

__device__ __forceinline__ float sigmoidf_(float v) { return 1.0f / (1.0f + expf(-v)); }

__device__ __forceinline__ uint32_t pack2(float lo, float hi) {
    __half2 p = __floats2half2_rn(lo, hi);
    return *reinterpret_cast<uint32_t*>(&p);
}

// ---------------------------------------------------------------------------
// Pack A = [x|h] -> fp16 row-major [M][K]. Fully coalesced.
// ---------------------------------------------------------------------------
__global__ __launch_bounds__(256)
void pack_a(const float* __restrict__ x, const float* __restrict__ h) {
    int idx = blockIdx.x * 256 + threadIdx.x;
    int m = idx >> 9;
    int j = (idx & 511) << 3;
    const float* src = (j < U_DIM) ? (x + (size_t)m * U_DIM + j)
                                   : (h + (size_t)m * U_DIM + (j - U_DIM));
    float4 v0 = reinterpret_cast<const float4*>(src)[0];
    float4 v1 = reinterpret_cast<const float4*>(src)[1];
    uint4 o;
    o.x = pack2(v0.x, v0.y);  o.y = pack2(v0.z, v0.w);
    o.z = pack2(v1.x, v1.y);  o.w = pack2(v1.z, v1.w);
    *reinterpret_cast<uint4*>(&g_ah[(size_t)m * K_DIM + j]) = o;
}

// ---------------------------------------------------------------------------
// Pack W [K][N] -> fp16 K-major [N][K] via 64x64 smem tile transpose.
// ---------------------------------------------------------------------------
__global__ __launch_bounds__(256)
void pack_w(const float* __restrict__ w) {
    __shared__ float st[64][65];
    int n0 = blockIdx.x * 64;
    int k0 = blockIdx.y * 64;
    int tid = threadIdx.x;
    int nx = tid & 63, ky = tid >> 6;
    #pragma unroll
    for (int r = 0; r < 16; ++r)
        st[ky + 4 * r][nx] = w[(size_t)(k0 + ky + 4 * r) * N_DIM + n0 + nx];
    __syncthreads();
    int kx = tid & 31, ny = tid >> 5;
    #pragma unroll
    for (int r = 0; r < 8; ++r) {
        int n = ny + 8 * r;
        uint32_t o = pack2(st[2 * kx][n], st[2 * kx + 1][n]);
        *reinterpret_cast<uint32_t*>(
            &g_wh[(size_t)(n0 + n) * K_DIM + k0 + 2 * kx]) = o;
    }
}

// ---------------------------------------------------------------------------
// Fused kernel: 512 threads, warp tile 32x32, ldmatrix + fp16 mma + gating
// ---------------------------------------------------------------------------
__global__ __launch_bounds__(512, 2)
void lstm_fused(const float* __restrict__ c, float* __restrict__ out) {
    extern __shared__ float smem[];
    const uint32_t smem_b = (uint32_t)__cvta_generic_to_shared(smem);
    const int tid = threadIdx.x;
    const int wid = tid >> 5, lane = tid & 31;
    const int g = lane >> 2, t = lane & 3;
    const int wm = wid >> 2, wn = wid & 3;        // 4 x 4 warps, tile 32x32
    const int bm = blockIdx.x * BM;
    const int bu = blockIdx.y * BUT;

    // ---- cp.async precompute: 4 chunks/thread (2 A + 2 B) ----
    const int crow = tid >> 3, cch = tid & 7;     // crow 0..63
    const __half* srcA = g_ah + (size_t)(bm + crow) * K_DIM + cch * 8;
    const __half* srcB0 = g_wh + (size_t)((crow >> 5) * U_DIM + bu + (crow & 31)) * K_DIM + cch * 8;
    const __half* srcB1 = g_wh + (size_t)((2 + (crow >> 5)) * U_DIM + bu + (crow & 31)) * K_DIM + cch * 8;
    const uint32_t dA = crow * 128 + ((cch ^ (crow & 7)) << 4);
    const uint32_t dB = B_OFF + dA;

    // ---- ldmatrix per-lane bases ----
    const int khA = lane >> 4;
    const int khB = (lane >> 3) & 1;
    uint32_t rowA[2], swA[2];
    #pragma unroll
    for (int mi = 0; mi < 2; ++mi) {
        int m = wm * 32 + mi * 16 + ((lane >> 3) & 1) * 8 + (lane & 7);
        rowA[mi] = m * 128;  swA[mi] = m & 7;
    }
    uint32_t rowB[2], swB[2];
    #pragma unroll
    for (int p = 0; p < 2; ++p) {
        int r = wn * 32 + p * 16 + (lane >> 4) * 8 + (lane & 7);
        rowB[p] = B_OFF + r * 128;  swB[p] = r & 7;
    }

    float acc[2][4][4];
    #pragma unroll
    for (int mi = 0; mi < 2; ++mi)
        #pragma unroll
        for (int ni = 0; ni < 4; ++ni)
            #pragma unroll
            for (int q = 0; q < 4; ++q) acc[mi][ni][q] = 0.0f;

    // prologue: stages 0, 1
    #pragma unroll
    for (int s = 0; s < 2; ++s) {
        uint32_t sb = smem_b + s * STG_BYTES;
        cp16(sb + dA, srcA);
        cp16(sb + dA + 8192, srcA + (size_t)64 * K_DIM);
        cp16(sb + dB, srcB0);
        cp16(sb + dB + 8192, srcB1);
        CP_COMMIT();
        srcA += BK;  srcB0 += BK;  srcB1 += BK;
    }

    int s_cur = 0, s_pre = 2;
    for (int kt = 0; kt < NKT; ++kt) {
        CP_WAIT1();
        __syncthreads();
        if (kt + 2 < NKT) {
            uint32_t sb = smem_b + s_pre * STG_BYTES;
            cp16(sb + dA, srcA);
            cp16(sb + dA + 8192, srcA + (size_t)64 * K_DIM);
            cp16(sb + dB, srcB0);
            cp16(sb + dB + 8192, srcB1);
            srcA += BK;  srcB0 += BK;  srcB1 += BK;
        }
        CP_COMMIT();

        const uint32_t sb = smem_b + s_cur * STG_BYTES;
        #pragma unroll
        for (int w = 0; w < 4; ++w) {
            const int kcA = 2 * w + khA;
            const int kcB = 2 * w + khB;
            uint32_t af[2][4];
            #pragma unroll
            for (int mi = 0; mi < 2; ++mi)
                ldsm4(af[mi], sb + rowA[mi] + ((kcA ^ swA[mi]) << 4));
            uint32_t bf[2][4];
            #pragma unroll
            for (int p = 0; p < 2; ++p)
                ldsm4(bf[p], sb + rowB[p] + ((kcB ^ swB[p]) << 4));
            #pragma unroll
            for (int mi = 0; mi < 2; ++mi)
                #pragma unroll
                for (int p = 0; p < 2; ++p)
                    #pragma unroll
                    for (int s2 = 0; s2 < 2; ++s2)
                        mma16(acc[mi][p * 2 + s2],
                              af[mi][0], af[mi][1], af[mi][2], af[mi][3],
                              bf[p][s2 * 2], bf[p][s2 * 2 + 1]);
        }

        s_cur = (s_cur + 1 == STAGES) ? 0 : s_cur + 1;
        s_pre = (s_pre + 1 == STAGES) ? 0 : s_pre + 1;
    }

    // ------------- epilogue: gather gates via smem, gate, write out ---------
    __syncthreads();
    float* se = smem;
    #pragma unroll
    for (int mi = 0; mi < 2; ++mi) {
        const int r0 = wm * 32 + mi * 16 + g;
        #pragma unroll
        for (int ni = 0; ni < 4; ++ni) {
            const int cb = wn * 32 + ni * 8 + 2 * t;
            *reinterpret_cast<float2*>(&se[r0 * EP_STRIDE + cb]) =
                make_float2(acc[mi][ni][0], acc[mi][ni][1]);
            *reinterpret_cast<float2*>(&se[(r0 + 8) * EP_STRIDE + cb]) =
                make_float2(acc[mi][ni][2], acc[mi][ni][3]);
        }
    }
    __syncthreads();

    const int BUsz = M_DIM * U_DIM;
    const int c4 = tid & 7;
    #pragma unroll
    for (int rep = 0; rep < 2; ++rep) {
        const int r = (tid >> 3) + rep * 64;
        const float* row = &se[r * EP_STRIDE];
        float4 iv = *reinterpret_cast<const float4*>(row + 0 * 32 + c4 * 4);
        float4 fv = *reinterpret_cast<const float4*>(row + 1 * 32 + c4 * 4);
        float4 gv = *reinterpret_cast<const float4*>(row + 2 * 32 + c4 * 4);
        float4 ov = *reinterpret_cast<const float4*>(row + 3 * 32 + c4 * 4);
        const size_t gidx = (size_t)(bm + r) * U_DIM + bu + c4 * 4;
        float4 cv = *reinterpret_cast<const float4*>(c + gidx);

        float ia[4] = {iv.x, iv.y, iv.z, iv.w};
        float fa[4] = {fv.x, fv.y, fv.z, fv.w};
        float ga[4] = {gv.x, gv.y, gv.z, gv.w};
        float oa[4] = {ov.x, ov.y, ov.z, ov.w};
        float ca[4] = {cv.x, cv.y, cv.z, cv.w};
        float hn[4], cn[4];
        #pragma unroll
        for (int q = 0; q < 4; ++q) {
            float ig = sigmoidf_(ia[q]);
            float fg = sigmoidf_(fa[q]);
            float og = sigmoidf_(oa[q]);
            float gg = tanhf(ga[q]);
            cn[q] = fg * ca[q] + ig * gg;
            hn[q] = og * tanhf(cn[q]);
        }
        float4 h4 = make_float4(hn[0], hn[1], hn[2], hn[3]);
        float4 cc4 = make_float4(cn[0], cn[1], cn[2], cn[3]);
        *reinterpret_cast<float4*>(out + gidx)            = h4;
        *reinterpret_cast<float4*>(out + BUsz + gidx)     = h4;
        *reinterpret_cast<float4*>(out + 2 * BUsz + gidx) = cc4;
    }
}

// ---------------------------------------------------------------------------
extern "C" void kernel_launch(void* const* d_in, const int* in_sizes, int n_in,
                              void* d_out, int out_size) {
    const float* x = (const float*)d_in[0];
    const float* h = (const float*)d_in[1];
    const float* c = (const float*)d_in[2];
    const float* w = (const float*)d_in[3];
    float* out = (float*)d_out;

    static int configured = 0;
    if (!configured) {
        cudaFuncSetAttribute(lstm_fused,
                             cudaFuncAttributeMaxDynamicSharedMemorySize,
                             SMEM_BYTES);
        configured = 1;
    }

    pack_a<<<(M_DIM * K_DIM / 8) / 256, 256>>>(x, h);
    pack_w<<<dim3(N_DIM / 64, K_DIM / 64), 256>>>(w);

    dim3 grid(M_DIM / BM, U_DIM / BUT);   // (8, 64); x fastest -> W L2 reuse
    lstm_fused<<<grid, 512, SMEM_BYTES>>>(c, out);
}

// round 13
// speedup vs baseline: 1.2620x; 1.2620x over previous
#include <cuda_runtime.h>
#include <cuda_fp16.h>
#include <cstdint>
#include <math.h>

#define M_DIM 1024
#define U_DIM 2048
#define N_DIM 8192
#define K_DIM 4096

#define BM 128
#define BUT 32
#define BK 64                                 // k per stage
#define STAGES 3
#define STG_BYTES 32768                       // A 16K + B 16K
#define SMEM_BYTES (STAGES * STG_BYTES)       // 98304 -> 2 CTAs/SM
#define B_OFF 16384
#define EP_STRIDE 132
#define NKT (K_DIM / BK)                      // 64

#define PACKA_BLOCKS 2048                     // M*K/8/256
#define PACKW_BLOCKS 8192                     // (N/64)*(K/64)

// Plain fp16 operands: A row-major [M][K]; W transposed K-major [N][K]
__device__ __align__(1024) __half g_ah[(size_t)M_DIM * K_DIM];   // 8 MB
__device__ __align__(1024) __half g_wh[(size_t)N_DIM * K_DIM];   // 64 MB

// ---------------------------------------------------------------------------
__device__ __forceinline__ void cp16(uint32_t dst, const void* src) {
    asm volatile("cp.async.cg.shared.global [%0], [%1], 16;" :: "r"(dst), "l"(src));
}
#define CP_COMMIT() asm volatile("cp.async.commit_group;" ::: "memory")
#define CP_WAIT1()  asm volatile("cp.async.wait_group 1;" ::: "memory")

__device__ __forceinline__ void ldsm4(uint32_t* r, uint32_t addr) {
    asm volatile("ldmatrix.sync.aligned.m8n8.x4.shared.b16 {%0,%1,%2,%3}, [%4];"
                 : "=r"(r[0]), "=r"(r[1]), "=r"(r[2]), "=r"(r[3]) : "r"(addr));
}

__device__ __forceinline__ void mma16(float* d, uint32_t a0, uint32_t a1,
                                      uint32_t a2, uint32_t a3,
                                      uint32_t b0, uint32_t b1) {
    asm volatile(
        "mma.sync.aligned.m16n8k16.row.col.f32.f16.f16.f32 "
        "{%0,%1,%2,%3}, {%4,%5,%6,%7}, {%8,%9}, {%0,%1,%2,%3};"
        : "+f"(d[0]), "+f"(d[1]), "+f"(d[2]), "+f"(d[3])
        : "r"(a0), "r"(a1), "r"(a2), "r"(a3), "r"(b0), "r"(b1));
}

__device__ __forceinline__ float sigmoidf_(float v) { return 1.0f / (1.0f + expf(-v)); }

__device__ __forceinline__ uint32_t pack2(float lo, float hi) {
    __half2 p = __floats2half2_rn(lo, hi);
    return *reinterpret_cast<uint32_t*>(&p);
}

// ---------------------------------------------------------------------------
// Merged pack kernel.
// Blocks [0, 2048): A = [x|h] -> fp16 row-major [M][K] (coalesced).
// Blocks [2048, 10240): W [K][N] -> fp16 K-major [N][K] (64x64 tile transpose).
// ---------------------------------------------------------------------------
__global__ __launch_bounds__(256)
void pack_all(const float* __restrict__ x, const float* __restrict__ h,
              const float* __restrict__ w) {
    __shared__ float st[64][65];
    if (blockIdx.x < PACKA_BLOCKS) {
        int idx = blockIdx.x * 256 + threadIdx.x;
        int m = idx >> 9;
        int j = (idx & 511) << 3;
        const float* src = (j < U_DIM) ? (x + (size_t)m * U_DIM + j)
                                       : (h + (size_t)m * U_DIM + (j - U_DIM));
        float4 v0 = reinterpret_cast<const float4*>(src)[0];
        float4 v1 = reinterpret_cast<const float4*>(src)[1];
        uint4 o;
        o.x = pack2(v0.x, v0.y);  o.y = pack2(v0.z, v0.w);
        o.z = pack2(v1.x, v1.y);  o.w = pack2(v1.z, v1.w);
        *reinterpret_cast<uint4*>(&g_ah[(size_t)m * K_DIM + j]) = o;
    } else {
        int blk = blockIdx.x - PACKA_BLOCKS;
        int n0 = (blk & 127) * 64;
        int k0 = (blk >> 7) * 64;
        int tid = threadIdx.x;
        int nx = tid & 63, ky = tid >> 6;
        #pragma unroll
        for (int r = 0; r < 16; ++r)
            st[ky + 4 * r][nx] = w[(size_t)(k0 + ky + 4 * r) * N_DIM + n0 + nx];
        __syncthreads();
        int kx = tid & 31, ny = tid >> 5;
        #pragma unroll
        for (int r = 0; r < 8; ++r) {
            int n = ny + 8 * r;
            uint32_t o = pack2(st[2 * kx][n], st[2 * kx + 1][n]);
            *reinterpret_cast<uint32_t*>(
                &g_wh[(size_t)(n0 + n) * K_DIM + k0 + 2 * kx]) = o;
        }
    }
}

// ---------------------------------------------------------------------------
// Fused kernel: ldmatrix + fp16 mma, software-pipelined fragments + gating
// ---------------------------------------------------------------------------
__global__ __launch_bounds__(256, 2)
void lstm_fused(const float* __restrict__ c, float* __restrict__ out) {
    extern __shared__ float smem[];
    const uint32_t smem_b = (uint32_t)__cvta_generic_to_shared(smem);
    const int tid = threadIdx.x;
    const int wid = tid >> 5, lane = tid & 31;
    const int g = lane >> 2, t = lane & 3;
    const int wm = wid >> 2, wn = wid & 3;        // 2 x 4 warps, warp tile 64x32
    const int bm = blockIdx.x * BM;
    const int bu = blockIdx.y * BUT;

    // ---- cp.async precompute: 8 chunks/thread (4 A + 4 B) ----
    const int crow = tid >> 3, cch = tid & 7;     // crow 0..31, cch 0..7
    const __half* srcA = g_ah + (size_t)(bm + crow) * K_DIM + cch * 8;
    const __half* srcB = g_wh + (size_t)(bu + crow) * K_DIM + cch * 8;
    const uint32_t dA = crow * 128 + ((cch ^ (crow & 7)) << 4);
    const uint32_t dB = B_OFF + dA;

    // ---- ldmatrix per-lane row bases ----
    const int khA = lane >> 4;
    const int khB = (lane >> 3) & 1;
    uint32_t rowA[4], swA[4];
    #pragma unroll
    for (int mi = 0; mi < 4; ++mi) {
        int m = wm * 64 + mi * 16 + ((lane >> 3) & 1) * 8 + (lane & 7);
        rowA[mi] = m * 128;  swA[mi] = m & 7;
    }
    uint32_t rowB[2], swB[2];
    #pragma unroll
    for (int p = 0; p < 2; ++p) {
        int r = wn * 32 + p * 16 + (lane >> 4) * 8 + (lane & 7);
        rowB[p] = B_OFF + r * 128;  swB[p] = r & 7;
    }

    float acc[4][4][4];
    #pragma unroll
    for (int mi = 0; mi < 4; ++mi)
        #pragma unroll
        for (int ni = 0; ni < 4; ++ni)
            #pragma unroll
            for (int q = 0; q < 4; ++q) acc[mi][ni][q] = 0.0f;

    // prologue: stages 0, 1
    #pragma unroll
    for (int s = 0; s < 2; ++s) {
        uint32_t sb = smem_b + s * STG_BYTES;
        #pragma unroll
        for (int i = 0; i < 4; ++i)
            cp16(sb + dA + i * 4096, srcA + (size_t)i * 32 * K_DIM);
        #pragma unroll
        for (int i = 0; i < 4; ++i)
            cp16(sb + dB + i * 4096, srcB + (size_t)i * U_DIM * K_DIM);
        CP_COMMIT();
        srcA += BK;  srcB += BK;
    }

    int s_cur = 0, s_pre = 2;
    for (int kt = 0; kt < NKT; ++kt) {
        CP_WAIT1();
        __syncthreads();
        if (kt + 2 < NKT) {
            uint32_t sb = smem_b + s_pre * STG_BYTES;
            #pragma unroll
            for (int i = 0; i < 4; ++i)
                cp16(sb + dA + i * 4096, srcA + (size_t)i * 32 * K_DIM);
            #pragma unroll
            for (int i = 0; i < 4; ++i)
                cp16(sb + dB + i * 4096, srcB + (size_t)i * U_DIM * K_DIM);
            srcA += BK;  srcB += BK;
        }
        CP_COMMIT();

        const uint32_t sb = smem_b + s_cur * STG_BYTES;

        // ---- software-pipelined fragment loads across the 4 k16 windows ----
        uint32_t af[2][4][4], bf[2][2][4];
        #pragma unroll
        for (int mi = 0; mi < 4; ++mi)
            ldsm4(af[0][mi], sb + rowA[mi] + ((khA ^ swA[mi]) << 4));
        #pragma unroll
        for (int p = 0; p < 2; ++p)
            ldsm4(bf[0][p], sb + rowB[p] + ((khB ^ swB[p]) << 4));

        #pragma unroll
        for (int w = 0; w < 4; ++w) {
            const int cur = w & 1, nxt = cur ^ 1;
            if (w < 3) {
                const int kA = 2 * (w + 1) + khA;
                const int kB = 2 * (w + 1) + khB;
                #pragma unroll
                for (int mi = 0; mi < 4; ++mi)
                    ldsm4(af[nxt][mi], sb + rowA[mi] + ((kA ^ swA[mi]) << 4));
                #pragma unroll
                for (int p = 0; p < 2; ++p)
                    ldsm4(bf[nxt][p], sb + rowB[p] + ((kB ^ swB[p]) << 4));
            }
            #pragma unroll
            for (int mi = 0; mi < 4; ++mi)
                #pragma unroll
                for (int p = 0; p < 2; ++p)
                    #pragma unroll
                    for (int s2 = 0; s2 < 2; ++s2)
                        mma16(acc[mi][p * 2 + s2],
                              af[cur][mi][0], af[cur][mi][1],
                              af[cur][mi][2], af[cur][mi][3],
                              bf[cur][p][s2 * 2], bf[cur][p][s2 * 2 + 1]);
        }

        s_cur = (s_cur + 1 == STAGES) ? 0 : s_cur + 1;
        s_pre = (s_pre + 1 == STAGES) ? 0 : s_pre + 1;
    }

    // ------------- epilogue: gather gates via smem, gate, write out ---------
    __syncthreads();
    float* se = smem;
    #pragma unroll
    for (int mi = 0; mi < 4; ++mi) {
        const int r0 = wm * 64 + mi * 16 + g;
        #pragma unroll
        for (int ni = 0; ni < 4; ++ni) {
            const int cb = wn * 32 + ni * 8 + 2 * t;
            *reinterpret_cast<float2*>(&se[r0 * EP_STRIDE + cb]) =
                make_float2(acc[mi][ni][0], acc[mi][ni][1]);
            *reinterpret_cast<float2*>(&se[(r0 + 8) * EP_STRIDE + cb]) =
                make_float2(acc[mi][ni][2], acc[mi][ni][3]);
        }
    }
    __syncthreads();

    const int BUsz = M_DIM * U_DIM;
    const int c4 = tid & 7;
    #pragma unroll
    for (int rep = 0; rep < 4; ++rep) {
        const int r = (tid >> 3) + rep * 32;
        const float* row = &se[r * EP_STRIDE];
        float4 iv = *reinterpret_cast<const float4*>(row + 0 * 32 + c4 * 4);
        float4 fv = *reinterpret_cast<const float4*>(row + 1 * 32 + c4 * 4);
        float4 gv = *reinterpret_cast<const float4*>(row + 2 * 32 + c4 * 4);
        float4 ov = *reinterpret_cast<const float4*>(row + 3 * 32 + c4 * 4);
        const size_t gidx = (size_t)(bm + r) * U_DIM + bu + c4 * 4;
        float4 cv = *reinterpret_cast<const float4*>(c + gidx);

        float ia[4] = {iv.x, iv.y, iv.z, iv.w};
        float fa[4] = {fv.x, fv.y, fv.z, fv.w};
        float ga[4] = {gv.x, gv.y, gv.z, gv.w};
        float oa[4] = {ov.x, ov.y, ov.z, ov.w};
        float ca[4] = {cv.x, cv.y, cv.z, cv.w};
        float hn[4], cn[4];
        #pragma unroll
        for (int q = 0; q < 4; ++q) {
            float ig = sigmoidf_(ia[q]);
            float fg = sigmoidf_(fa[q]);
            float og = sigmoidf_(oa[q]);
            float gg = tanhf(ga[q]);
            cn[q] = fg * ca[q] + ig * gg;
            hn[q] = og * tanhf(cn[q]);
        }
        float4 h4 = make_float4(hn[0], hn[1], hn[2], hn[3]);
        float4 cc4 = make_float4(cn[0], cn[1], cn[2], cn[3]);
        *reinterpret_cast<float4*>(out + gidx)            = h4;
        *reinterpret_cast<float4*>(out + BUsz + gidx)     = h4;
        *reinterpret_cast<float4*>(out + 2 * BUsz + gidx) = cc4;
    }
}

// ---------------------------------------------------------------------------
extern "C" void kernel_launch(void* const* d_in, const int* in_sizes, int n_in,
                              void* d_out, int out_size) {
    const float* x = (const float*)d_in[0];
    const float* h = (const float*)d_in[1];
    const float* c = (const float*)d_in[2];
    const float* w = (const float*)d_in[3];
    float* out = (float*)d_out;

    static int configured = 0;
    if (!configured) {
        cudaFuncSetAttribute(lstm_fused,
                             cudaFuncAttributeMaxDynamicSharedMemorySize,
                             SMEM_BYTES);
        configured = 1;
    }

    pack_all<<<PACKA_BLOCKS + PACKW_BLOCKS, 256>>>(x, h, w);

    dim3 grid(M_DIM / BM, U_DIM / BUT);   // (8, 64); x fastest -> W L2 reuse
    lstm_fused<<<grid, 256, SMEM_BYTES>>>(c, out);
}